// round 13
// baseline (speedup 1.0000x reference)
#include <cuda_runtime.h>
#include <cuda_fp16.h>
#include <math.h>
#include <stdint.h>

#define T_TOK 8192
#define D_DIM 1024
#define I_DIM 2048
#define E_NUM 8
#define MAXROWS 17408
#define MAXTILES 136

// prep_kernel block partition
#define ROUTER_B 1024
#define CONV_B   1536
#define ZERO_B   256

// ---------------- scratch (device globals) -----------------------------------
__device__ __align__(128) __half g_H16[(size_t)MAXROWS * I_DIM];
__device__ __align__(128) __half g_x16[(size_t)T_TOK * D_DIM];
__device__ __align__(128) __half g_gw16[(size_t)E_NUM * D_DIM * I_DIM];
__device__ __align__(128) __half g_uw16[(size_t)E_NUM * D_DIM * I_DIM];
__device__ __align__(128) __half g_dw16[(size_t)E_NUM * I_DIM * D_DIM];
__device__ int   g_tok[MAXROWS];
__device__ float g_wt[MAXROWS];
__device__ int   g_e[T_TOK * 2];
__device__ float g_w[T_TOK * 2];
__device__ int   g_fill[E_NUM];
__device__ int   g_base[E_NUM + 1];
__device__ int   g_tileoff[E_NUM + 1];

// ---------------- helpers ----------------------------------------------------
__device__ __forceinline__ unsigned smem_u32(const void* p) {
    return (unsigned)__cvta_generic_to_shared(p);
}
__device__ __forceinline__ unsigned swzB(unsigned o) { return o ^ ((o >> 3) & 0x70u); }

__device__ __forceinline__ void cp_async16(unsigned dst, const void* src) {
    asm volatile("cp.async.cg.shared.global [%0], [%1], 16;\n" :: "r"(dst), "l"(src));
}
__device__ __forceinline__ void cp_commit() { asm volatile("cp.async.commit_group;\n"); }
__device__ __forceinline__ void cp_wait1() { asm volatile("cp.async.wait_group 1;\n"); }
__device__ __forceinline__ void cp_wait0() { asm volatile("cp.async.wait_group 0;\n"); }

__device__ __forceinline__ void ldsm_x4(unsigned* r, unsigned a) {
    asm volatile("ldmatrix.sync.aligned.m8n8.x4.shared.b16 {%0,%1,%2,%3}, [%4];"
                 : "=r"(r[0]), "=r"(r[1]), "=r"(r[2]), "=r"(r[3]) : "r"(a));
}
__device__ __forceinline__ void ldsm_x4t(unsigned* r, unsigned a) {
    asm volatile("ldmatrix.sync.aligned.m8n8.x4.trans.shared.b16 {%0,%1,%2,%3}, [%4];"
                 : "=r"(r[0]), "=r"(r[1]), "=r"(r[2]), "=r"(r[3]) : "r"(a));
}
#define MMA_F16(C, A, B) \
    asm volatile("mma.sync.aligned.m16n8k16.row.col.f32.f16.f16.f32 " \
                 "{%0,%1,%2,%3},{%4,%5,%6,%7},{%8,%9},{%0,%1,%2,%3};" \
                 : "+f"(C[0]), "+f"(C[1]), "+f"(C[2]), "+f"(C[3]) \
                 : "r"(A[0]), "r"(A[1]), "r"(A[2]), "r"(A[3]), "r"(B[0]), "r"(B[1]))

// ============================================================================
// prep: fused zero(out) + weight fp16 convert + router (+ x fp16 convert)
// ============================================================================
__global__ void prep_kernel(const float* __restrict__ x,
                            const float* __restrict__ rw,
                            const float* __restrict__ rb,
                            const float* __restrict__ gw,
                            const float* __restrict__ uw,
                            const float* __restrict__ dw,
                            float* __restrict__ out, int out_elems) {
    __shared__ float s_rw[E_NUM * D_DIM];
    int b = blockIdx.x;
    int tid = threadIdx.x;

    if (b >= ROUTER_B + CONV_B) {
        int b3 = b - (ROUTER_B + CONV_B);
        for (int i = b3 * 256 + tid; i < out_elems; i += ZERO_B * 256) out[i] = 0.0f;
        return;
    }
    if (b >= ROUTER_B) {
        int b2 = b - ROUTER_B;
        const size_t N2 = (size_t)E_NUM * D_DIM * I_DIM / 2;
        size_t i0 = (size_t)b2 * 256 + tid;
        size_t stride = (size_t)CONV_B * 256;
        __half2* pg = (__half2*)g_gw16;
        __half2* pu = (__half2*)g_uw16;
        __half2* pd = (__half2*)g_dw16;
        const float2* sg = (const float2*)gw;
        const float2* su = (const float2*)uw;
        const float2* sd = (const float2*)dw;
        for (size_t i = i0; i < N2; i += stride) {
            pg[i] = __float22half2_rn(sg[i]);
            pu[i] = __float22half2_rn(su[i]);
            pd[i] = __float22half2_rn(sd[i]);
        }
        return;
    }

    // ---- router: 8 tokens per block ----
    {
        size_t off = (size_t)b * 8 * D_DIM;
        const float2* src = (const float2*)(x + off);
        __half2* dst = (__half2*)(g_x16 + off);
        for (int i = tid; i < 8 * D_DIM / 2; i += 256)
            dst[i] = __float22half2_rn(src[i]);
    }
    for (int i = tid; i < E_NUM * D_DIM; i += 256)
        s_rw[(i & 7) * D_DIM + (i >> 3)] = rw[i];
    __syncthreads();

    int wid = tid >> 5, lane = tid & 31;
    int t = b * 8 + wid;
    if (t >= T_TOK) return;
    float acc[E_NUM];
#pragma unroll
    for (int e = 0; e < E_NUM; e++) acc[e] = 0.0f;
    const float* xr = x + (size_t)t * D_DIM;
    for (int k = lane; k < D_DIM; k += 32) {
        float xv = xr[k];
#pragma unroll
        for (int e = 0; e < E_NUM; e++) acc[e] += xv * s_rw[e * D_DIM + k];
    }
#pragma unroll
    for (int e = 0; e < E_NUM; e++) {
        float v = acc[e];
#pragma unroll
        for (int o = 16; o > 0; o >>= 1) v += __shfl_xor_sync(0xffffffffu, v, o);
        acc[e] = v;
    }
    if (lane == 0) {
        float l[E_NUM];
#pragma unroll
        for (int e = 0; e < E_NUM; e++) l[e] = acc[e] + rb[e];
        int b0 = 0; float v0 = l[0];
#pragma unroll
        for (int e = 1; e < E_NUM; e++) if (l[e] > v0) { v0 = l[e]; b0 = e; }
        int b1 = -1; float v1 = -1e30f;
#pragma unroll
        for (int e = 0; e < E_NUM; e++) if (e != b0 && l[e] > v1) { v1 = l[e]; b1 = e; }
        float q = expf(v1 - v0);
        float w0 = 1.0f / (1.0f + q);
        float w1 = q * w0;
        g_e[2 * t] = b0; g_e[2 * t + 1] = b1;
        g_w[2 * t] = w0; g_w[2 * t + 1] = w1;
    }
}

// ---------------- scan: histogram + bases + pad -------------------------------
__global__ void scan_kernel() {
    __shared__ int s_cnt[E_NUM];
    __shared__ int s_base[E_NUM + 1];
    int tid = threadIdx.x;
    if (tid < E_NUM) s_cnt[tid] = 0;
    __syncthreads();
    {
        int loc[E_NUM];
#pragma unroll
        for (int e = 0; e < E_NUM; e++) loc[e] = 0;
        for (int i = tid; i < 2 * T_TOK; i += 256) loc[g_e[i]]++;
#pragma unroll
        for (int e = 0; e < E_NUM; e++)
            if (loc[e]) atomicAdd(&s_cnt[e], loc[e]);
    }
    __syncthreads();
    if (tid == 0) {
        int acc = 0, tacc = 0;
        for (int e = 0; e < E_NUM; e++) {
            int c = s_cnt[e];
            g_base[e] = acc; s_base[e] = acc;
            g_tileoff[e] = tacc;
            int pad = ((c + 127) / 128) * 128;
            acc += pad; tacc += pad / 128;
            g_fill[e] = 0;
        }
        g_base[E_NUM] = acc; s_base[E_NUM] = acc;
        g_tileoff[E_NUM] = tacc;
    }
    __syncthreads();
    for (int e = 0; e < E_NUM; e++) {
        int lo = s_base[e] + s_cnt[e], hi = s_base[e + 1];
        for (int s = lo + tid; s < hi; s += 256) {
            g_tok[s] = -1; g_wt[s] = 0.0f;
        }
    }
}

// ---------------- scatter ------------------------------------------------------
__global__ void scatter_kernel() {
    int t = blockIdx.x * blockDim.x + threadIdx.x;
    if (t >= T_TOK) return;
#pragma unroll
    for (int k = 0; k < 2; k++) {
        int e = g_e[2 * t + k];
        int pos = atomicAdd(&g_fill[e], 1);
        int slot = g_base[e] + pos;
        g_tok[slot] = t;
        g_wt[slot] = g_w[2 * t + k];
    }
}

// ============================================================================
// GEMM1 (fp16 mma.sync): CTA 128x128, gate+up fused, BK=64, 4 stages,
// 2 kt per barrier.
// ============================================================================
#define G1_STAGE 49152
#define G1_NK    16

__global__ __launch_bounds__(256, 1)
void gemm1_kernel(const float* __restrict__ gate_b, const float* __restrict__ up_b) {
    extern __shared__ __half dynsmem[];
    __shared__ int s_tok[128];
    __shared__ float s_gb[128], s_ub[128];

    int fm = blockIdx.y;
    if (fm >= g_tileoff[E_NUM]) return;
    int e = 0;
    while (fm >= g_tileoff[e + 1]) e++;
    int row0 = g_base[e] + (fm - g_tileoff[e]) * 128;
    int n0 = blockIdx.x * 128;

    int tid = threadIdx.x;
    int wid = tid >> 5, lane = tid & 31;
    unsigned base = smem_u32(dynsmem);

    if (tid < 128) s_tok[tid] = g_tok[row0 + tid];
    __syncthreads();

    const __half* a_src[4]; unsigned a_soff[4];
#pragma unroll
    for (int i = 0; i < 4; i++) {
        int f = tid + i * 256;
        int r = f >> 3, c16 = f & 7;
        int tok = s_tok[r];
        a_src[i] = g_x16 + (size_t)(tok < 0 ? 0 : tok) * D_DIM + c16 * 8;
        a_soff[i] = swzB((unsigned)(r * 128 + c16 * 16));
    }
    unsigned b_soff[4]; size_t b_goff[4];
#pragma unroll
    for (int i = 0; i < 4; i++) {
        int f = tid + i * 256;
        int nb = f >> 9, g = f & 511;
        int krow = g >> 3, c16 = g & 7;
        b_soff[i] = (unsigned)(nb * 8192) + swzB((unsigned)(krow * 128 + c16 * 16));
        b_goff[i] = (size_t)krow * I_DIM + nb * 64 + c16 * 8;
    }
    const __half* gw_e = g_gw16 + (size_t)e * D_DIM * I_DIM + n0;
    const __half* uw_e = g_uw16 + (size_t)e * D_DIM * I_DIM + n0;

    auto fill = [&](int st, int kt) {
        unsigned sA = base + (unsigned)st * G1_STAGE;
        unsigned sBg = sA + 16384u, sBu = sA + 32768u;
        size_t kw = (size_t)kt * 64 * I_DIM;
#pragma unroll
        for (int i = 0; i < 4; i++) cp_async16(sA + a_soff[i], a_src[i] + kt * 64);
#pragma unroll
        for (int i = 0; i < 4; i++) cp_async16(sBg + b_soff[i], gw_e + kw + b_goff[i]);
#pragma unroll
        for (int i = 0; i < 4; i++) cp_async16(sBu + b_soff[i], uw_e + kw + b_goff[i]);
        cp_commit();
    };

    fill(0, 0); fill(1, 1);

    float cg[4][4][4], cu[4][4][4];
#pragma unroll
    for (int mi = 0; mi < 4; mi++)
#pragma unroll
        for (int ni = 0; ni < 4; ni++)
#pragma unroll
            for (int r = 0; r < 4; r++) { cg[mi][ni][r] = 0.0f; cu[mi][ni][r] = 0.0f; }

    int wm = wid >> 2, wn = wid & 3;
    int l15 = lane & 15, lh = lane >> 4;

    for (int kt = 0; kt < G1_NK; kt += 2) {
        cp_wait0();
        __syncthreads();
        if (kt + 2 < G1_NK) fill((kt + 2) & 3, kt + 2);
        if (kt + 3 < G1_NK) fill((kt + 3) & 3, kt + 3);

#pragma unroll
        for (int kp = 0; kp < 2; kp++) {
            unsigned sA = base + (unsigned)((kt + kp) & 3) * G1_STAGE;
            unsigned sBg = sA + 16384u, sBu = sA + 32768u;
#pragma unroll
            for (int ks = 0; ks < 4; ks++) {
                unsigned a[4][4];
#pragma unroll
                for (int mi = 0; mi < 4; mi++) {
                    int r = wm * 64 + mi * 16 + l15;
                    ldsm_x4(a[mi], sA + swzB((unsigned)(r * 128 + (ks * 2 + lh) * 16)));
                }
                unsigned bg[4][2], bu[4][2];
                int kr = ks * 16 + l15;
#pragma unroll
                for (int nip = 0; nip < 2; nip++) {
                    int ncta = wn * 32 + (nip * 2 + lh) * 8;
                    unsigned off = (unsigned)((ncta >> 6) * 8192) +
                                   swzB((unsigned)(kr * 128 + ((ncta & 63) >> 3) * 16));
                    unsigned t4[4];
                    ldsm_x4t(t4, sBg + off);
                    bg[nip * 2][0] = t4[0]; bg[nip * 2][1] = t4[1];
                    bg[nip * 2 + 1][0] = t4[2]; bg[nip * 2 + 1][1] = t4[3];
                    ldsm_x4t(t4, sBu + off);
                    bu[nip * 2][0] = t4[0]; bu[nip * 2][1] = t4[1];
                    bu[nip * 2 + 1][0] = t4[2]; bu[nip * 2 + 1][1] = t4[3];
                }
#pragma unroll
                for (int mi = 0; mi < 4; mi++)
#pragma unroll
                    for (int ni = 0; ni < 4; ni++) {
                        MMA_F16(cg[mi][ni], a[mi], bg[ni]);
                        MMA_F16(cu[mi][ni], a[mi], bu[ni]);
                    }
            }
        }
    }

    __syncthreads();
    if (tid < 128) {
        s_gb[tid] = gate_b[e * I_DIM + n0 + tid];
        s_ub[tid] = up_b[e * I_DIM + n0 + tid];
    }
    __syncthreads();

    int gp = lane >> 2, tig = lane & 3;
#pragma unroll
    for (int mi = 0; mi < 4; mi++) {
#pragma unroll
        for (int ni = 0; ni < 4; ni++) {
            int rl = wm * 64 + mi * 16 + gp;
            int colL = wn * 32 + ni * 8 + tig * 2;
            float gb0 = s_gb[colL], gb1 = s_gb[colL + 1];
            float ub0 = s_ub[colL], ub1 = s_ub[colL + 1];
#pragma unroll
            for (int rr = 0; rr < 2; rr++) {
                int row = row0 + rl + rr * 8;
                float g0 = cg[mi][ni][rr * 2 + 0] + gb0;
                float g1 = cg[mi][ni][rr * 2 + 1] + gb1;
                float u0 = cu[mi][ni][rr * 2 + 0] + ub0;
                float u1 = cu[mi][ni][rr * 2 + 1] + ub1;
                float h0 = g0 / (1.0f + expf(-g0)) * u0;
                float h1 = g1 / (1.0f + expf(-g1)) * u1;
                *(__half2*)&g_H16[(size_t)row * I_DIM + n0 + colL] =
                    __floats2half2_rn(h0, h1);
            }
        }
    }
}

// ============================================================================
// GEMM2 (fp16): H16[128] x down_w -> 128 cols, K=2048, BK=64, 3-stage, occ 2.
// ============================================================================
#define G2_STAGE 32768
#define G2_NK    32

__global__ __launch_bounds__(256, 2)
void gemm2_kernel(const float* __restrict__ down_b, float* __restrict__ out) {
    extern __shared__ __half dynsmem[];
    __shared__ int s_tok[128];
    __shared__ float s_wt[128];
    __shared__ float s_db[128];

    int fm = blockIdx.y;
    if (fm >= g_tileoff[E_NUM]) return;
    int e = 0;
    while (fm >= g_tileoff[e + 1]) e++;
    int row0 = g_base[e] + (fm - g_tileoff[e]) * 128;
    int n0 = blockIdx.x * 128;

    int tid = threadIdx.x;
    int wid = tid >> 5, lane = tid & 31;
    unsigned base = smem_u32(dynsmem);

    if (tid < 128) { s_tok[tid] = g_tok[row0 + tid]; s_wt[tid] = g_wt[row0 + tid]; }
    __syncthreads();

    const __half* a_src[4]; unsigned a_soff[4];
#pragma unroll
    for (int i = 0; i < 4; i++) {
        int f = tid + i * 256;
        int r = f >> 3, c16 = f & 7;
        a_src[i] = g_H16 + (size_t)(row0 + r) * I_DIM + c16 * 8;
        a_soff[i] = swzB((unsigned)(r * 128 + c16 * 16));
    }
    unsigned b_soff[4]; size_t b_goff[4];
#pragma unroll
    for (int i = 0; i < 4; i++) {
        int f = tid + i * 256;
        int nb = f >> 9, g = f & 511;
        int krow = g >> 3, c16 = g & 7;
        b_soff[i] = (unsigned)(nb * 8192) + swzB((unsigned)(krow * 128 + c16 * 16));
        b_goff[i] = (size_t)krow * D_DIM + nb * 64 + c16 * 8;
    }
    const __half* dw_e = g_dw16 + (size_t)e * I_DIM * D_DIM + n0;

    auto fill = [&](int st, int kt) {
        unsigned sA = base + (unsigned)st * G2_STAGE;
        unsigned sB = sA + 16384u;
        size_t kw = (size_t)kt * 64 * D_DIM;
#pragma unroll
        for (int i = 0; i < 4; i++) cp_async16(sA + a_soff[i], a_src[i] + kt * 64);
#pragma unroll
        for (int i = 0; i < 4; i++) cp_async16(sB + b_soff[i], dw_e + kw + b_goff[i]);
        cp_commit();
    };

    fill(0, 0); fill(1, 1);

    float c[4][4][4];
#pragma unroll
    for (int mi = 0; mi < 4; mi++)
#pragma unroll
        for (int ni = 0; ni < 4; ni++)
#pragma unroll
            for (int r = 0; r < 4; r++) c[mi][ni][r] = 0.0f;

    int wm = wid >> 2, wn = wid & 3;
    int l15 = lane & 15, lh = lane >> 4;

    int cur = 0;
    for (int kt = 0; kt < G2_NK; kt++) {
        if (kt + 1 < G2_NK) cp_wait1(); else cp_wait0();
        __syncthreads();
        if (kt + 2 < G2_NK) {
            int nx = cur + 2; if (nx >= 3) nx -= 3;
            fill(nx, kt + 2);
        }

        unsigned sA = base + (unsigned)cur * G2_STAGE;
        unsigned sB = sA + 16384u;

#pragma unroll
        for (int ks = 0; ks < 4; ks++) {
            unsigned a[4][4];
#pragma unroll
            for (int mi = 0; mi < 4; mi++) {
                int r = wm * 64 + mi * 16 + l15;
                ldsm_x4(a[mi], sA + swzB((unsigned)(r * 128 + (ks * 2 + lh) * 16)));
            }
            unsigned b[4][2];
            int kr = ks * 16 + l15;
#pragma unroll
            for (int nip = 0; nip < 2; nip++) {
                int ncta = wn * 32 + (nip * 2 + lh) * 8;
                unsigned off = (unsigned)((ncta >> 6) * 8192) +
                               swzB((unsigned)(kr * 128 + ((ncta & 63) >> 3) * 16));
                unsigned t4[4];
                ldsm_x4t(t4, sB + off);
                b[nip * 2][0] = t4[0]; b[nip * 2][1] = t4[1];
                b[nip * 2 + 1][0] = t4[2]; b[nip * 2 + 1][1] = t4[3];
            }
#pragma unroll
            for (int mi = 0; mi < 4; mi++)
#pragma unroll
                for (int ni = 0; ni < 4; ni++)
                    MMA_F16(c[mi][ni], a[mi], b[ni]);
        }
        if (++cur >= 3) cur = 0;
    }

    __syncthreads();
    if (tid < 128) s_db[tid] = down_b[e * D_DIM + n0 + tid];
    __syncthreads();

    int gp = lane >> 2, tig = lane & 3;
#pragma unroll
    for (int mi = 0; mi < 4; mi++) {
#pragma unroll
        for (int ni = 0; ni < 4; ni++) {
            int colL = wn * 32 + ni * 8 + tig * 2;
            int col = n0 + colL;
            float db0 = s_db[colL], db1 = s_db[colL + 1];
#pragma unroll
            for (int rr = 0; rr < 2; rr++) {
                int rl = wm * 64 + mi * 16 + gp + rr * 8;
                int tok = s_tok[rl];
                if (tok < 0) continue;
                float w = s_wt[rl];
                atomicAdd(&out[(size_t)tok * D_DIM + col],
                          w * (c[mi][ni][rr * 2 + 0] + db0));
                atomicAdd(&out[(size_t)tok * D_DIM + col + 1],
                          w * (c[mi][ni][rr * 2 + 1] + db1));
            }
        }
    }
}

// ---------------- host launcher ----------------------------------------------
extern "C" void kernel_launch(void* const* d_in, const int* in_sizes, int n_in,
                              void* d_out, int out_size) {
    const float* x  = (const float*)d_in[0];
    const float* rw = (const float*)d_in[1];
    const float* rb = (const float*)d_in[2];
    const float* gw = (const float*)d_in[3];
    const float* gb = (const float*)d_in[4];
    const float* uw = (const float*)d_in[5];
    const float* ub = (const float*)d_in[6];
    const float* dw = (const float*)d_in[7];
    const float* db = (const float*)d_in[8];
    float* out = (float*)d_out;

    cudaFuncSetAttribute(gemm1_kernel, cudaFuncAttributeMaxDynamicSharedMemorySize, 4 * G1_STAGE);
    cudaFuncSetAttribute(gemm2_kernel, cudaFuncAttributeMaxDynamicSharedMemorySize, 3 * G2_STAGE);

    prep_kernel<<<ROUTER_B + CONV_B + ZERO_B, 256>>>(x, rw, rb, gw, uw, dw, out, out_size);
    scan_kernel<<<1, 256>>>();
    scatter_kernel<<<T_TOK / 256, 256>>>();
    gemm1_kernel<<<dim3(I_DIM / 128, MAXTILES), 256, 4 * G1_STAGE>>>(gb, ub);
    gemm2_kernel<<<dim3(D_DIM / 128, MAXTILES), 256, 3 * G2_STAGE>>>(db, out);
}

// round 14
// speedup vs baseline: 1.0264x; 1.0264x over previous
#include <cuda_runtime.h>
#include <cuda_fp16.h>
#include <math.h>
#include <stdint.h>

#define T_TOK 8192
#define D_DIM 1024
#define I_DIM 2048
#define E_NUM 8
#define MAXROWS 17408
#define MAXTILES 136

// prep_kernel block partition
#define ROUTER_B 1024
#define CONV_B   1536
#define ZERO_B   256

// ---------------- scratch (device globals) -----------------------------------
__device__ __align__(128) __half g_H16[(size_t)MAXROWS * I_DIM];
__device__ __align__(128) __half g_x16[(size_t)T_TOK * D_DIM];
__device__ __align__(128) __half g_gw16[(size_t)E_NUM * D_DIM * I_DIM];
__device__ __align__(128) __half g_uw16[(size_t)E_NUM * D_DIM * I_DIM];
__device__ __align__(128) __half g_dw16[(size_t)E_NUM * I_DIM * D_DIM];
__device__ int   g_tok[MAXROWS];
__device__ float g_wt[MAXROWS];
__device__ int   g_e[T_TOK * 2];
__device__ float g_w[T_TOK * 2];
__device__ int   g_fill[E_NUM];
__device__ int   g_base[E_NUM + 1];
__device__ int   g_tileoff[E_NUM + 1];

// ---------------- helpers ----------------------------------------------------
__device__ __forceinline__ unsigned smem_u32(const void* p) {
    return (unsigned)__cvta_generic_to_shared(p);
}
__device__ __forceinline__ unsigned swzB(unsigned o) { return o ^ ((o >> 3) & 0x70u); }

__device__ __forceinline__ void cp_async16(unsigned dst, const void* src) {
    asm volatile("cp.async.cg.shared.global [%0], [%1], 16;\n" :: "r"(dst), "l"(src));
}
__device__ __forceinline__ void cp_commit() { asm volatile("cp.async.commit_group;\n"); }
__device__ __forceinline__ void cp_wait1() { asm volatile("cp.async.wait_group 1;\n"); }
__device__ __forceinline__ void cp_wait0() { asm volatile("cp.async.wait_group 0;\n"); }

__device__ __forceinline__ void ldsm_x4(unsigned* r, unsigned a) {
    asm volatile("ldmatrix.sync.aligned.m8n8.x4.shared.b16 {%0,%1,%2,%3}, [%4];"
                 : "=r"(r[0]), "=r"(r[1]), "=r"(r[2]), "=r"(r[3]) : "r"(a));
}
__device__ __forceinline__ void ldsm_x4t(unsigned* r, unsigned a) {
    asm volatile("ldmatrix.sync.aligned.m8n8.x4.trans.shared.b16 {%0,%1,%2,%3}, [%4];"
                 : "=r"(r[0]), "=r"(r[1]), "=r"(r[2]), "=r"(r[3]) : "r"(a));
}
#define MMA_F16(C, A, B) \
    asm volatile("mma.sync.aligned.m16n8k16.row.col.f32.f16.f16.f32 " \
                 "{%0,%1,%2,%3},{%4,%5,%6,%7},{%8,%9},{%0,%1,%2,%3};" \
                 : "+f"(C[0]), "+f"(C[1]), "+f"(C[2]), "+f"(C[3]) \
                 : "r"(A[0]), "r"(A[1]), "r"(A[2]), "r"(A[3]), "r"(B[0]), "r"(B[1]))

// ============================================================================
// prep: fused zero(out) + weight fp16 convert + router (+ x fp16 convert)
// ============================================================================
__global__ void prep_kernel(const float* __restrict__ x,
                            const float* __restrict__ rw,
                            const float* __restrict__ rb,
                            const float* __restrict__ gw,
                            const float* __restrict__ uw,
                            const float* __restrict__ dw,
                            float* __restrict__ out, int out_elems) {
    __shared__ float s_rw[E_NUM * D_DIM];
    int b = blockIdx.x;
    int tid = threadIdx.x;

    if (b >= ROUTER_B + CONV_B) {
        int b3 = b - (ROUTER_B + CONV_B);
        for (int i = b3 * 256 + tid; i < out_elems; i += ZERO_B * 256) out[i] = 0.0f;
        return;
    }
    if (b >= ROUTER_B) {
        int b2 = b - ROUTER_B;
        const size_t N2 = (size_t)E_NUM * D_DIM * I_DIM / 2;
        size_t i0 = (size_t)b2 * 256 + tid;
        size_t stride = (size_t)CONV_B * 256;
        __half2* pg = (__half2*)g_gw16;
        __half2* pu = (__half2*)g_uw16;
        __half2* pd = (__half2*)g_dw16;
        const float2* sg = (const float2*)gw;
        const float2* su = (const float2*)uw;
        const float2* sd = (const float2*)dw;
        for (size_t i = i0; i < N2; i += stride) {
            pg[i] = __float22half2_rn(sg[i]);
            pu[i] = __float22half2_rn(su[i]);
            pd[i] = __float22half2_rn(sd[i]);
        }
        return;
    }

    // ---- router: 8 tokens per block ----
    {
        size_t off = (size_t)b * 8 * D_DIM;
        const float2* src = (const float2*)(x + off);
        __half2* dst = (__half2*)(g_x16 + off);
        for (int i = tid; i < 8 * D_DIM / 2; i += 256)
            dst[i] = __float22half2_rn(src[i]);
    }
    for (int i = tid; i < E_NUM * D_DIM; i += 256)
        s_rw[(i & 7) * D_DIM + (i >> 3)] = rw[i];
    __syncthreads();

    int wid = tid >> 5, lane = tid & 31;
    int t = b * 8 + wid;
    if (t >= T_TOK) return;
    float acc[E_NUM];
#pragma unroll
    for (int e = 0; e < E_NUM; e++) acc[e] = 0.0f;
    const float* xr = x + (size_t)t * D_DIM;
    for (int k = lane; k < D_DIM; k += 32) {
        float xv = xr[k];
#pragma unroll
        for (int e = 0; e < E_NUM; e++) acc[e] += xv * s_rw[e * D_DIM + k];
    }
#pragma unroll
    for (int e = 0; e < E_NUM; e++) {
        float v = acc[e];
#pragma unroll
        for (int o = 16; o > 0; o >>= 1) v += __shfl_xor_sync(0xffffffffu, v, o);
        acc[e] = v;
    }
    if (lane == 0) {
        float l[E_NUM];
#pragma unroll
        for (int e = 0; e < E_NUM; e++) l[e] = acc[e] + rb[e];
        int b0 = 0; float v0 = l[0];
#pragma unroll
        for (int e = 1; e < E_NUM; e++) if (l[e] > v0) { v0 = l[e]; b0 = e; }
        int b1 = -1; float v1 = -1e30f;
#pragma unroll
        for (int e = 0; e < E_NUM; e++) if (e != b0 && l[e] > v1) { v1 = l[e]; b1 = e; }
        float q = expf(v1 - v0);
        float w0 = 1.0f / (1.0f + q);
        float w1 = q * w0;
        g_e[2 * t] = b0; g_e[2 * t + 1] = b1;
        g_w[2 * t] = w0; g_w[2 * t + 1] = w1;
    }
}

// ---------------- scan: histogram + bases + pad -------------------------------
__global__ void scan_kernel() {
    __shared__ int s_cnt[E_NUM];
    __shared__ int s_base[E_NUM + 1];
    int tid = threadIdx.x;
    if (tid < E_NUM) s_cnt[tid] = 0;
    __syncthreads();
    {
        int loc[E_NUM];
#pragma unroll
        for (int e = 0; e < E_NUM; e++) loc[e] = 0;
        for (int i = tid; i < 2 * T_TOK; i += 256) loc[g_e[i]]++;
#pragma unroll
        for (int e = 0; e < E_NUM; e++)
            if (loc[e]) atomicAdd(&s_cnt[e], loc[e]);
    }
    __syncthreads();
    if (tid == 0) {
        int acc = 0, tacc = 0;
        for (int e = 0; e < E_NUM; e++) {
            int c = s_cnt[e];
            g_base[e] = acc; s_base[e] = acc;
            g_tileoff[e] = tacc;
            int pad = ((c + 127) / 128) * 128;
            acc += pad; tacc += pad / 128;
            g_fill[e] = 0;
        }
        g_base[E_NUM] = acc; s_base[E_NUM] = acc;
        g_tileoff[E_NUM] = tacc;
    }
    __syncthreads();
    for (int e = 0; e < E_NUM; e++) {
        int lo = s_base[e] + s_cnt[e], hi = s_base[e + 1];
        for (int s = lo + tid; s < hi; s += 256) {
            g_tok[s] = -1; g_wt[s] = 0.0f;
        }
    }
}

// ---------------- scatter ------------------------------------------------------
__global__ void scatter_kernel() {
    int t = blockIdx.x * blockDim.x + threadIdx.x;
    if (t >= T_TOK) return;
#pragma unroll
    for (int k = 0; k < 2; k++) {
        int e = g_e[2 * t + k];
        int pos = atomicAdd(&g_fill[e], 1);
        int slot = g_base[e] + pos;
        g_tok[slot] = t;
        g_wt[slot] = g_w[2 * t + k];
    }
}

// ============================================================================
// GEMM1 (fp16 mma.sync): CTA 128x128, gate+up fused, BK=64, 4 stages,
// 512 threads = 4m x 4n warps, warp tile 32x32 per matrix. 2 kt per barrier.
// ============================================================================
#define G1_STAGE 49152
#define G1_NK    16
#define G1_THR   512

__global__ __launch_bounds__(G1_THR, 1)
void gemm1_kernel(const float* __restrict__ gate_b, const float* __restrict__ up_b) {
    extern __shared__ __half dynsmem[];
    __shared__ int s_tok[128];
    __shared__ float s_gb[128], s_ub[128];

    int fm = blockIdx.y;
    if (fm >= g_tileoff[E_NUM]) return;
    int e = 0;
    while (fm >= g_tileoff[e + 1]) e++;
    int row0 = g_base[e] + (fm - g_tileoff[e]) * 128;
    int n0 = blockIdx.x * 128;

    int tid = threadIdx.x;
    int wid = tid >> 5, lane = tid & 31;
    unsigned base = smem_u32(dynsmem);

    if (tid < 128) s_tok[tid] = g_tok[row0 + tid];
    __syncthreads();

    // A: 1024 16B-chunks, 2 per thread
    const __half* a_src[2]; unsigned a_soff[2];
#pragma unroll
    for (int i = 0; i < 2; i++) {
        int f = tid + i * G1_THR;
        int r = f >> 3, c16 = f & 7;
        int tok = s_tok[r];
        a_src[i] = g_x16 + (size_t)(tok < 0 ? 0 : tok) * D_DIM + c16 * 8;
        a_soff[i] = swzB((unsigned)(r * 128 + c16 * 16));
    }
    // B: 1024 chunks per matrix, 2 per thread
    unsigned b_soff[2]; size_t b_goff[2];
#pragma unroll
    for (int i = 0; i < 2; i++) {
        int f = tid + i * G1_THR;
        int nb = f >> 9, g = f & 511;
        int krow = g >> 3, c16 = g & 7;
        b_soff[i] = (unsigned)(nb * 8192) + swzB((unsigned)(krow * 128 + c16 * 16));
        b_goff[i] = (size_t)krow * I_DIM + nb * 64 + c16 * 8;
    }
    const __half* gw_e = g_gw16 + (size_t)e * D_DIM * I_DIM + n0;
    const __half* uw_e = g_uw16 + (size_t)e * D_DIM * I_DIM + n0;

    auto fill = [&](int st, int kt) {
        unsigned sA = base + (unsigned)st * G1_STAGE;
        unsigned sBg = sA + 16384u, sBu = sA + 32768u;
        size_t kw = (size_t)kt * 64 * I_DIM;
#pragma unroll
        for (int i = 0; i < 2; i++) cp_async16(sA + a_soff[i], a_src[i] + kt * 64);
#pragma unroll
        for (int i = 0; i < 2; i++) cp_async16(sBg + b_soff[i], gw_e + kw + b_goff[i]);
#pragma unroll
        for (int i = 0; i < 2; i++) cp_async16(sBu + b_soff[i], uw_e + kw + b_goff[i]);
        cp_commit();
    };

    fill(0, 0); fill(1, 1);

    float cg[2][4][4], cu[2][4][4];
#pragma unroll
    for (int mi = 0; mi < 2; mi++)
#pragma unroll
        for (int ni = 0; ni < 4; ni++)
#pragma unroll
            for (int r = 0; r < 4; r++) { cg[mi][ni][r] = 0.0f; cu[mi][ni][r] = 0.0f; }

    int wm = wid >> 2, wn = wid & 3;   // 4x4 warp grid
    int l15 = lane & 15, lh = lane >> 4;

    for (int kt = 0; kt < G1_NK; kt += 2) {
        cp_wait0();
        __syncthreads();
        if (kt + 2 < G1_NK) fill((kt + 2) & 3, kt + 2);
        if (kt + 3 < G1_NK) fill((kt + 3) & 3, kt + 3);

#pragma unroll
        for (int kp = 0; kp < 2; kp++) {
            unsigned sA = base + (unsigned)((kt + kp) & 3) * G1_STAGE;
            unsigned sBg = sA + 16384u, sBu = sA + 32768u;
#pragma unroll
            for (int ks = 0; ks < 4; ks++) {
                unsigned a[2][4];
#pragma unroll
                for (int mi = 0; mi < 2; mi++) {
                    int r = wm * 32 + mi * 16 + l15;
                    ldsm_x4(a[mi], sA + swzB((unsigned)(r * 128 + (ks * 2 + lh) * 16)));
                }
                unsigned bg[4][2], bu[4][2];
                int kr = ks * 16 + l15;
#pragma unroll
                for (int nip = 0; nip < 2; nip++) {
                    int ncta = wn * 32 + (nip * 2 + lh) * 8;
                    unsigned off = (unsigned)((ncta >> 6) * 8192) +
                                   swzB((unsigned)(kr * 128 + ((ncta & 63) >> 3) * 16));
                    unsigned t4[4];
                    ldsm_x4t(t4, sBg + off);
                    bg[nip * 2][0] = t4[0]; bg[nip * 2][1] = t4[1];
                    bg[nip * 2 + 1][0] = t4[2]; bg[nip * 2 + 1][1] = t4[3];
                    ldsm_x4t(t4, sBu + off);
                    bu[nip * 2][0] = t4[0]; bu[nip * 2][1] = t4[1];
                    bu[nip * 2 + 1][0] = t4[2]; bu[nip * 2 + 1][1] = t4[3];
                }
#pragma unroll
                for (int mi = 0; mi < 2; mi++)
#pragma unroll
                    for (int ni = 0; ni < 4; ni++) {
                        MMA_F16(cg[mi][ni], a[mi], bg[ni]);
                        MMA_F16(cu[mi][ni], a[mi], bu[ni]);
                    }
            }
        }
    }

    __syncthreads();
    if (tid < 128) {
        s_gb[tid] = gate_b[e * I_DIM + n0 + tid];
        s_ub[tid] = up_b[e * I_DIM + n0 + tid];
    }
    __syncthreads();

    int gp = lane >> 2, tig = lane & 3;
#pragma unroll
    for (int mi = 0; mi < 2; mi++) {
#pragma unroll
        for (int ni = 0; ni < 4; ni++) {
            int rl = wm * 32 + mi * 16 + gp;
            int colL = wn * 32 + ni * 8 + tig * 2;
            float gb0 = s_gb[colL], gb1 = s_gb[colL + 1];
            float ub0 = s_ub[colL], ub1 = s_ub[colL + 1];
#pragma unroll
            for (int rr = 0; rr < 2; rr++) {
                int row = row0 + rl + rr * 8;
                float g0 = cg[mi][ni][rr * 2 + 0] + gb0;
                float g1 = cg[mi][ni][rr * 2 + 1] + gb1;
                float u0 = cu[mi][ni][rr * 2 + 0] + ub0;
                float u1 = cu[mi][ni][rr * 2 + 1] + ub1;
                float h0 = g0 / (1.0f + expf(-g0)) * u0;
                float h1 = g1 / (1.0f + expf(-g1)) * u1;
                *(__half2*)&g_H16[(size_t)row * I_DIM + n0 + colL] =
                    __floats2half2_rn(h0, h1);
            }
        }
    }
}

// ============================================================================
// GEMM2 (fp16): H16[128] x down_w -> 128 cols, K=2048, BK=64, 3-stage, occ 2.
// ============================================================================
#define G2_STAGE 32768
#define G2_NK    32

__global__ __launch_bounds__(256, 2)
void gemm2_kernel(const float* __restrict__ down_b, float* __restrict__ out) {
    extern __shared__ __half dynsmem[];
    __shared__ int s_tok[128];
    __shared__ float s_wt[128];
    __shared__ float s_db[128];

    int fm = blockIdx.y;
    if (fm >= g_tileoff[E_NUM]) return;
    int e = 0;
    while (fm >= g_tileoff[e + 1]) e++;
    int row0 = g_base[e] + (fm - g_tileoff[e]) * 128;
    int n0 = blockIdx.x * 128;

    int tid = threadIdx.x;
    int wid = tid >> 5, lane = tid & 31;
    unsigned base = smem_u32(dynsmem);

    if (tid < 128) { s_tok[tid] = g_tok[row0 + tid]; s_wt[tid] = g_wt[row0 + tid]; }
    __syncthreads();

    const __half* a_src[4]; unsigned a_soff[4];
#pragma unroll
    for (int i = 0; i < 4; i++) {
        int f = tid + i * 256;
        int r = f >> 3, c16 = f & 7;
        a_src[i] = g_H16 + (size_t)(row0 + r) * I_DIM + c16 * 8;
        a_soff[i] = swzB((unsigned)(r * 128 + c16 * 16));
    }
    unsigned b_soff[4]; size_t b_goff[4];
#pragma unroll
    for (int i = 0; i < 4; i++) {
        int f = tid + i * 256;
        int nb = f >> 9, g = f & 511;
        int krow = g >> 3, c16 = g & 7;
        b_soff[i] = (unsigned)(nb * 8192) + swzB((unsigned)(krow * 128 + c16 * 16));
        b_goff[i] = (size_t)krow * D_DIM + nb * 64 + c16 * 8;
    }
    const __half* dw_e = g_dw16 + (size_t)e * I_DIM * D_DIM + n0;

    auto fill = [&](int st, int kt) {
        unsigned sA = base + (unsigned)st * G2_STAGE;
        unsigned sB = sA + 16384u;
        size_t kw = (size_t)kt * 64 * D_DIM;
#pragma unroll
        for (int i = 0; i < 4; i++) cp_async16(sA + a_soff[i], a_src[i] + kt * 64);
#pragma unroll
        for (int i = 0; i < 4; i++) cp_async16(sB + b_soff[i], dw_e + kw + b_goff[i]);
        cp_commit();
    };

    fill(0, 0); fill(1, 1);

    float c[4][4][4];
#pragma unroll
    for (int mi = 0; mi < 4; mi++)
#pragma unroll
        for (int ni = 0; ni < 4; ni++)
#pragma unroll
            for (int r = 0; r < 4; r++) c[mi][ni][r] = 0.0f;

    int wm = wid >> 2, wn = wid & 3;
    int l15 = lane & 15, lh = lane >> 4;

    int cur = 0;
    for (int kt = 0; kt < G2_NK; kt++) {
        if (kt + 1 < G2_NK) cp_wait1(); else cp_wait0();
        __syncthreads();
        if (kt + 2 < G2_NK) {
            int nx = cur + 2; if (nx >= 3) nx -= 3;
            fill(nx, kt + 2);
        }

        unsigned sA = base + (unsigned)cur * G2_STAGE;
        unsigned sB = sA + 16384u;

#pragma unroll
        for (int ks = 0; ks < 4; ks++) {
            unsigned a[4][4];
#pragma unroll
            for (int mi = 0; mi < 4; mi++) {
                int r = wm * 64 + mi * 16 + l15;
                ldsm_x4(a[mi], sA + swzB((unsigned)(r * 128 + (ks * 2 + lh) * 16)));
            }
            unsigned b[4][2];
            int kr = ks * 16 + l15;
#pragma unroll
            for (int nip = 0; nip < 2; nip++) {
                int ncta = wn * 32 + (nip * 2 + lh) * 8;
                unsigned off = (unsigned)((ncta >> 6) * 8192) +
                               swzB((unsigned)(kr * 128 + ((ncta & 63) >> 3) * 16));
                unsigned t4[4];
                ldsm_x4t(t4, sB + off);
                b[nip * 2][0] = t4[0]; b[nip * 2][1] = t4[1];
                b[nip * 2 + 1][0] = t4[2]; b[nip * 2 + 1][1] = t4[3];
            }
#pragma unroll
            for (int mi = 0; mi < 4; mi++)
#pragma unroll
                for (int ni = 0; ni < 4; ni++)
                    MMA_F16(c[mi][ni], a[mi], b[ni]);
        }
        if (++cur >= 3) cur = 0;
    }

    __syncthreads();
    if (tid < 128) s_db[tid] = down_b[e * D_DIM + n0 + tid];
    __syncthreads();

    int gp = lane >> 2, tig = lane & 3;
#pragma unroll
    for (int mi = 0; mi < 4; mi++) {
#pragma unroll
        for (int ni = 0; ni < 4; ni++) {
            int colL = wn * 32 + ni * 8 + tig * 2;
            int col = n0 + colL;
            float db0 = s_db[colL], db1 = s_db[colL + 1];
#pragma unroll
            for (int rr = 0; rr < 2; rr++) {
                int rl = wm * 64 + mi * 16 + gp + rr * 8;
                int tok = s_tok[rl];
                if (tok < 0) continue;
                float w = s_wt[rl];
                atomicAdd(&out[(size_t)tok * D_DIM + col],
                          w * (c[mi][ni][rr * 2 + 0] + db0));
                atomicAdd(&out[(size_t)tok * D_DIM + col + 1],
                          w * (c[mi][ni][rr * 2 + 1] + db1));
            }
        }
    }
}

// ---------------- host launcher ----------------------------------------------
extern "C" void kernel_launch(void* const* d_in, const int* in_sizes, int n_in,
                              void* d_out, int out_size) {
    const float* x  = (const float*)d_in[0];
    const float* rw = (const float*)d_in[1];
    const float* rb = (const float*)d_in[2];
    const float* gw = (const float*)d_in[3];
    const float* gb = (const float*)d_in[4];
    const float* uw = (const float*)d_in[5];
    const float* ub = (const float*)d_in[6];
    const float* dw = (const float*)d_in[7];
    const float* db = (const float*)d_in[8];
    float* out = (float*)d_out;

    cudaFuncSetAttribute(gemm1_kernel, cudaFuncAttributeMaxDynamicSharedMemorySize, 4 * G1_STAGE);
    cudaFuncSetAttribute(gemm2_kernel, cudaFuncAttributeMaxDynamicSharedMemorySize, 3 * G2_STAGE);

    prep_kernel<<<ROUTER_B + CONV_B + ZERO_B, 256>>>(x, rw, rb, gw, uw, dw, out, out_size);
    scan_kernel<<<1, 256>>>();
    scatter_kernel<<<T_TOK / 256, 256>>>();
    gemm1_kernel<<<dim3(I_DIM / 128, MAXTILES), G1_THR, 4 * G1_STAGE>>>(gb, ub);
    gemm2_kernel<<<dim3(D_DIM / 128, MAXTILES), 256, 3 * G2_STAGE>>>(db, out);
}